// round 16
// baseline (speedup 1.0000x reference)
#include <cuda_runtime.h>
#include <math.h>

#define HC 128
#define N2MAX 96000
#define MAXCELLS 65536

// ---------------- scratch (static device globals; no allocation) ----------------
__device__ __align__(16) float g_A[N2MAX * HC];
__device__ __align__(16) float g_B[N2MAX * HC];
__device__ __align__(16) float g_C[N2MAX * HC];
__device__ float g_dinv0[16000];
__device__ float g_dinv1[32000];
__device__ float g_dinv2[96000];
__device__ float g_tp0[16000 * 3];
__device__ float g_tp1[32000 * 3];
__device__ float g_tp2[96000 * 3];
__device__ int   g_idx01[32000 * 3];
__device__ float g_d201[32000 * 3];
__device__ int   g_idx12[N2MAX * 3];
__device__ float g_d212[N2MAX * 3];

// edge sort scratch (built on side stream)
__device__ int g_ecnt[N2MAX];
__device__ int g_ecur[N2MAX];
__device__ int g_srow0[128000], g_scol0[128000];
__device__ int g_srow1[256000], g_scol1[256000];
__device__ int g_srow2[768000], g_scol2[768000];

// grid kNN scratch — separate per stage
struct GridParams { float ox, oy, oz, h, invh; int Gx, Gy, Gz, Rmax; };
__device__ unsigned g_bbox0[6];
__device__ unsigned g_bbox1[6];
__device__ GridParams g_gp0, g_gp1;
__device__ int g_cellCnt0[MAXCELLS], g_cellStart0[MAXCELLS + 1], g_cellCur0[MAXCELLS];
__device__ int g_cellCnt1[MAXCELLS], g_cellStart1[MAXCELLS + 1], g_cellCur1[MAXCELLS];
__device__ __align__(16) float4 g_spts0[16000];
__device__ int g_sidx0[16000];
__device__ __align__(16) float4 g_spts1[32000];
__device__ int g_sidx1[32000];
// query binning (knn12 only)
__device__ int g_qCnt1[MAXCELLS], g_qStart1[MAXCELLS + 1], g_qCur1[MAXCELLS];
__device__ __align__(16) float4 g_sq12[N2MAX];
__device__ int g_qperm12[N2MAX];

// ---------------- helpers ----------------
__device__ __forceinline__ unsigned fkey(float f) {
    unsigned u = __float_as_uint(f);
    return (u & 0x80000000u) ? ~u : (u | 0x80000000u);
}
__device__ __forceinline__ float fdec(unsigned k) {
    return (k & 0x80000000u) ? __uint_as_float(k ^ 0x80000000u) : __uint_as_float(~k);
}
__device__ __forceinline__ float selu_f(float v) {
    const float alpha = 1.6732632423543772f;
    const float scale = 1.0507009873554805f;
    return scale * (v > 0.f ? v : alpha * expm1f(v));
}
__device__ __forceinline__ void ffma2(unsigned long long& d, unsigned long long a, unsigned long long b) {
    asm("fma.rn.f32x2 %0, %1, %2, %0;" : "+l"(d) : "l"(a), "l"(b));
}
__device__ __forceinline__ unsigned long long splat2(float w) {
    unsigned long long r;
    asm("mov.b64 %0, {%1, %1};" : "=l"(r) : "f"(w));
    return r;
}
__device__ __forceinline__ void unpack2(unsigned long long v, float& lo, float& hi) {
    asm("mov.b64 {%0, %1}, %2;" : "=f"(lo), "=f"(hi) : "l"(v));
}
__device__ __forceinline__ void red4(float* dst, float4 v) {
    asm volatile("red.global.add.v4.f32 [%0], {%1,%2,%3,%4};"
                 :: "l"(dst), "f"(v.x), "f"(v.y), "f"(v.z), "f"(v.w) : "memory");
}

// ---------------- grid kNN ----------------

__global__ void initbbox_kernel(unsigned* bbox) {
    int i = threadIdx.x;
    if (i < 6) bbox[i] = (i < 3) ? 0xFFFFFFFFu : 0u;
}

__global__ void transform_kernel(const float* __restrict__ pos, int n,
                                 float* __restrict__ out, unsigned* bbox) {
    int i = blockIdx.x * blockDim.x + threadIdx.x;
    bool valid = (i < n);
    float x = 0.f, y = 0.f, z = 0.f;
    if (valid) { x = pos[3 * i]; y = pos[3 * i + 1]; z = pos[3 * i + 2]; }
    float nx = x - 0.57735026918962576f * y;
    float s = 1.0f + 0.78571428571428571f * (y / 1.1963f);
    float ox = nx * s, oy = y * s, oz = z * s;
    if (valid) { out[3 * i] = ox; out[3 * i + 1] = oy; out[3 * i + 2] = oz; }
    if (bbox) {
        unsigned kx = valid ? fkey(ox) : 0xFFFFFFFFu;
        unsigned ky = valid ? fkey(oy) : 0xFFFFFFFFu;
        unsigned kz = valid ? fkey(oz) : 0xFFFFFFFFu;
        unsigned mnx = __reduce_min_sync(0xFFFFFFFFu, kx);
        unsigned mny = __reduce_min_sync(0xFFFFFFFFu, ky);
        unsigned mnz = __reduce_min_sync(0xFFFFFFFFu, kz);
        unsigned mxx = __reduce_max_sync(0xFFFFFFFFu, valid ? kx : 0u);
        unsigned mxy = __reduce_max_sync(0xFFFFFFFFu, valid ? ky : 0u);
        unsigned mxz = __reduce_max_sync(0xFFFFFFFFu, valid ? kz : 0u);
        if ((threadIdx.x & 31) == 0) {
            atomicMin(&bbox[0], mnx); atomicMin(&bbox[1], mny); atomicMin(&bbox[2], mnz);
            atomicMax(&bbox[3], mxx); atomicMax(&bbox[4], mxy); atomicMax(&bbox[5], mxz);
        }
    }
}

__global__ void gridparams_kernel(const unsigned* __restrict__ bbox, int np, GridParams* gpout) {
    if (threadIdx.x != 0 || blockIdx.x != 0) return;
    float ox = fdec(bbox[0]), oy = fdec(bbox[1]), oz = fdec(bbox[2]);
    float mx = fdec(bbox[3]), my = fdec(bbox[4]), mz = fdec(bbox[5]);
    float ex = mx - ox, ey = my - oy, ez = mz - oz;
    float em = fmaxf(ex, fmaxf(ey, ez));
    float eps = 1e-4f * em + 1e-6f;
    ox -= eps; oy -= eps; oz -= eps;
    ex += 2.f * eps; ey += 2.f * eps; ez += 2.f * eps;
    int target = np / 2; if (target < 1) target = 1;
    float h = cbrtf(ex * ey * ez / (float)target);
    if (h < 1e-6f) h = 1e-6f;
    int Gx, Gy, Gz;
    for (int it = 0; it < 64; it++) {
        Gx = (int)(ex / h) + 1; Gy = (int)(ey / h) + 1; Gz = (int)(ez / h) + 1;
        if (Gx < 1) Gx = 1; if (Gy < 1) Gy = 1; if (Gz < 1) Gz = 1;
        long long prod = (long long)Gx * Gy * Gz;
        if (prod <= MAXCELLS) break;
        h *= 1.0905f;
    }
    GridParams gp;
    gp.ox = ox; gp.oy = oy; gp.oz = oz; gp.h = h; gp.invh = 1.0f / h;
    gp.Gx = Gx; gp.Gy = Gy; gp.Gz = Gz;
    gp.Rmax = max(Gx, max(Gy, Gz));
    *gpout = gp;
}

__global__ void zeroints_kernel(int* __restrict__ a, int n) {
    int i = blockIdx.x * blockDim.x + threadIdx.x;
    if (i < n) a[i] = 0;
}

__global__ void zero2_kernel(int* __restrict__ a, int* __restrict__ b, int n) {
    int i = blockIdx.x * blockDim.x + threadIdx.x;
    if (i < n) { a[i] = 0; b[i] = 0; }
}

__device__ __forceinline__ int cell_of(float x, float y, float z, const GridParams& gp) {
    int cx = (int)floorf((x - gp.ox) * gp.invh);
    int cy = (int)floorf((y - gp.oy) * gp.invh);
    int cz = (int)floorf((z - gp.oz) * gp.invh);
    cx = min(max(cx, 0), gp.Gx - 1);
    cy = min(max(cy, 0), gp.Gy - 1);
    cz = min(max(cz, 0), gp.Gz - 1);
    return (cz * gp.Gy + cy) * gp.Gx + cx;
}

__global__ void gridcount_kernel(const float* __restrict__ p, int np,
                                 const GridParams* __restrict__ gpp, int* __restrict__ cnt) {
    int i = blockIdx.x * blockDim.x + threadIdx.x;
    if (i >= np) return;
    GridParams gp = *gpp;
    int c = cell_of(p[3 * i], p[3 * i + 1], p[3 * i + 2], gp);
    atomicAdd(&cnt[c], 1);
}

__global__ void __launch_bounds__(1024) scan_kernel(const int* __restrict__ cnt,
                                                    int* __restrict__ start,
                                                    int* __restrict__ cur) {
    __shared__ int ssum[1024];
    int tid = threadIdx.x;
    const int PER = MAXCELLS / 1024;
    int base = tid * PER;
    int sum = 0;
    for (int i = 0; i < PER; i++) sum += cnt[base + i];
    ssum[tid] = sum;
    __syncthreads();
    for (int off = 1; off < 1024; off <<= 1) {
        int v = (tid >= off) ? ssum[tid - off] : 0;
        __syncthreads();
        ssum[tid] += v;
        __syncthreads();
    }
    int run = ssum[tid] - sum;
    for (int i = 0; i < PER; i++) {
        start[base + i] = run;
        cur[base + i] = run;
        run += cnt[base + i];
    }
    if (tid == 1023) start[MAXCELLS] = run;
}

__global__ void gridscatter_kernel(const float* __restrict__ p, int np,
                                   const GridParams* __restrict__ gpp, int* __restrict__ cur,
                                   float4* __restrict__ spts, int* __restrict__ sidx) {
    int i = blockIdx.x * blockDim.x + threadIdx.x;
    if (i >= np) return;
    GridParams gp = *gpp;
    float x = p[3 * i], y = p[3 * i + 1], z = p[3 * i + 2];
    int c = cell_of(x, y, z, gp);
    int pos = atomicAdd(&cur[c], 1);
    float p2 = x * x;
    p2 = fmaf(y, y, p2);
    p2 = fmaf(z, z, p2);
    spts[pos] = make_float4(x, y, z, p2);
    sidx[pos] = i;
}

// bin queries: count, then scatter sorted coords (x,y,z,|q|^2) + perm
__global__ void qcount_kernel(const float* __restrict__ q, int nq,
                              const GridParams* __restrict__ gpp, int* __restrict__ cnt) {
    int i = blockIdx.x * blockDim.x + threadIdx.x;
    if (i >= nq) return;
    GridParams gp = *gpp;
    int c = cell_of(q[3 * i], q[3 * i + 1], q[3 * i + 2], gp);
    atomicAdd(&cnt[c], 1);
}

__global__ void qscatter_kernel(const float* __restrict__ q, int nq,
                                const GridParams* __restrict__ gpp, int* __restrict__ cur,
                                float4* __restrict__ sq, int* __restrict__ perm) {
    int i = blockIdx.x * blockDim.x + threadIdx.x;
    if (i >= nq) return;
    GridParams gp = *gpp;
    float x = q[3 * i], y = q[3 * i + 1], z = q[3 * i + 2];
    int c = cell_of(x, y, z, gp);
    int pos = atomicAdd(&cur[c], 1);
    float qq = x * x;
    qq = fmaf(y, y, qq);
    qq = fmaf(z, z, qq);
    sq[pos] = make_float4(x, y, z, qq);
    perm[pos] = i;
}

#define KNN_SCAN_SPAN(S_, E_)                                                   \
    for (int j_ = (S_); j_ < (E_); j_++) {                                      \
        float4 pt = spts[j_];                                                   \
        float dot = qx * pt.x;                                                  \
        dot = fmaf(qy, pt.y, dot);                                              \
        dot = fmaf(qz, pt.z, dot);                                              \
        float d = fmaf(-2.0f, dot, qq) + pt.w;                                  \
        if (d < b2) {                                                           \
            int gi = sidx[j_];                                                  \
            if (d < b0)      { b2 = b1; i2 = i1; b1 = b0; i1 = i0; b0 = d; i0 = gi; } \
            else if (d < b1) { b2 = b1; i2 = i1; b1 = d; i1 = gi; }             \
            else             { b2 = d; i2 = gi; }                               \
        }                                                                       \
    }

#define KNN_BODY                                                                \
    int ccx = (int)floorf((qx - gp.ox) * gp.invh);                              \
    int ccy = (int)floorf((qy - gp.oy) * gp.invh);                              \
    int ccz = (int)floorf((qz - gp.oz) * gp.invh);                              \
    ccx = min(max(ccx, 0), gp.Gx - 1);                                          \
    ccy = min(max(ccy, 0), gp.Gy - 1);                                          \
    ccz = min(max(ccz, 0), gp.Gz - 1);                                          \
    float b0 = 1e30f, b1 = 1e30f, b2 = 1e30f;                                   \
    int i0 = 0, i1 = 0, i2 = 0;                                                 \
    {                                                                           \
        int c = (ccz * gp.Gy + ccy) * gp.Gx + ccx;                              \
        int s = cellStart[c], e = cellStart[c + 1];                             \
        KNN_SCAN_SPAN(s, e);                                                    \
    }                                                                           \
    for (int r = 1; r <= gp.Rmax; r++) {                                        \
        float dm = (float)(r - 1) * gp.h;                                       \
        if (b2 <= dm * dm) break;                                               \
        for (int dz = -r; dz <= r; dz++) {                                      \
            int z = ccz + dz;                                                   \
            if (z < 0 || z >= gp.Gz) continue;                                  \
            bool zface = (dz == -r) || (dz == r);                               \
            for (int dy = -r; dy <= r; dy++) {                                  \
                int y = ccy + dy;                                               \
                if (y < 0 || y >= gp.Gy) continue;                              \
                bool face = zface || (dy == -r) || (dy == r);                   \
                int rowbase = (z * gp.Gy + y) * gp.Gx;                          \
                if (face) {                                                     \
                    int x0 = max(ccx - r, 0), x1 = min(ccx + r, gp.Gx - 1);     \
                    int s = cellStart[rowbase + x0], e = cellStart[rowbase + x1 + 1]; \
                    KNN_SCAN_SPAN(s, e);                                        \
                } else {                                                        \
                    int x = ccx - r;                                            \
                    if (x >= 0) {                                               \
                        int s = cellStart[rowbase + x], e = cellStart[rowbase + x + 1]; \
                        KNN_SCAN_SPAN(s, e);                                    \
                    }                                                           \
                    x = ccx + r;                                                \
                    if (x < gp.Gx) {                                            \
                        int s = cellStart[rowbase + x], e = cellStart[rowbase + x + 1]; \
                        KNN_SCAN_SPAN(s, e);                                    \
                    }                                                           \
                }                                                               \
            }                                                                   \
        }                                                                       \
    }

__global__ void __launch_bounds__(128) gridknn_kernel(
    const float* __restrict__ q, int nq,
    const GridParams* __restrict__ gpp, const int* __restrict__ cellStart,
    const float4* __restrict__ spts, const int* __restrict__ sidx,
    int* __restrict__ oidx, float* __restrict__ od2) {
    int qi = blockIdx.x * blockDim.x + threadIdx.x;
    if (qi >= nq) return;
    GridParams gp = *gpp;
    float qx = q[3 * qi], qy = q[3 * qi + 1], qz = q[3 * qi + 2];
    float qq = qx * qx;
    qq = fmaf(qy, qy, qq);
    qq = fmaf(qz, qz, qq);
    KNN_BODY
    oidx[qi * 3] = i0; oidx[qi * 3 + 1] = i1; oidx[qi * 3 + 2] = i2;
    od2[qi * 3] = b0;  od2[qi * 3 + 1] = b1;  od2[qi * 3 + 2] = b2;
}

// sorted-query variant: coalesced coord reads, scattered (small) output writes
__global__ void __launch_bounds__(128) gridknn_sorted_kernel(
    const float4* __restrict__ sq, const int* __restrict__ perm, int nq,
    const GridParams* __restrict__ gpp, const int* __restrict__ cellStart,
    const float4* __restrict__ spts, const int* __restrict__ sidx,
    int* __restrict__ oidx, float* __restrict__ od2) {
    int t = blockIdx.x * blockDim.x + threadIdx.x;
    if (t >= nq) return;
    GridParams gp = *gpp;
    float4 qv = sq[t];
    float qx = qv.x, qy = qv.y, qz = qv.z, qq = qv.w;
    KNN_BODY
    int qi = perm[t];
    oidx[qi * 3] = i0; oidx[qi * 3 + 1] = i1; oidx[qi * 3 + 2] = i2;
    od2[qi * 3] = b0;  od2[qi * 3 + 1] = b1;  od2[qi * 3 + 2] = b2;
}

// ---------------- edge sort (counting sort by col) + dinv ----------------

__global__ void countint_kernel(const int* __restrict__ col, int E, int* __restrict__ cnt) {
    int e = blockIdx.x * blockDim.x + threadIdx.x;
    if (e < E) atomicAdd(&cnt[col[e]], 1);
}

__global__ void __launch_bounds__(1024) scanN_kernel(const int* __restrict__ cnt, int n,
                                                     int* __restrict__ cur) {
    __shared__ int ssum[1024];
    int tid = threadIdx.x;
    int per = (n + 1023) >> 10;
    int base = tid * per;
    int sum = 0;
    for (int i = 0; i < per; i++) {
        int c = base + i;
        if (c < n) sum += cnt[c];
    }
    ssum[tid] = sum;
    __syncthreads();
    for (int off = 1; off < 1024; off <<= 1) {
        int v = (tid >= off) ? ssum[tid - off] : 0;
        __syncthreads();
        ssum[tid] += v;
        __syncthreads();
    }
    int run = ssum[tid] - sum;
    for (int i = 0; i < per; i++) {
        int c = base + i;
        if (c < n) { cur[c] = run; run += cnt[c]; }
    }
}

__global__ void dinvcnt_kernel(const int* __restrict__ cnt, float* __restrict__ d, int n) {
    int i = blockIdx.x * blockDim.x + threadIdx.x;
    if (i < n) d[i] = rsqrtf((float)cnt[i] + 1.0f);
}

__global__ void sortfill_kernel(const int* __restrict__ row, const int* __restrict__ col, int E,
                                int* __restrict__ cur, int* __restrict__ srow, int* __restrict__ scol) {
    int e = blockIdx.x * blockDim.x + threadIdx.x;
    if (e >= E) return;
    int c = col[e];
    int p = atomicAdd(&cur[c], 1);
    srow[p] = row[e];
    scol[p] = c;
}

// ---------------- dense ops (FFMA2) ----------------

__global__ void __launch_bounds__(256) linear_selu_kernel(
    const float* __restrict__ latent, const float* __restrict__ W,
    const float* __restrict__ b, int n, float* __restrict__ out) {
    const int NT = 32;
    __shared__ __align__(16) float sIn[64][NT + 4];
    int base = blockIdx.x * NT;
    int tid = threadIdx.x;
    for (int i = tid; i < NT * 64; i += 256) {
        int r = i >> 6, c = i & 63;
        int node = base + r;
        sIn[c][r] = (node < n) ? latent[node * 64 + c] : 0.f;
    }
    __syncthreads();
    int ch = tid & 127, half = tid >> 7;
    unsigned long long acc[8];
#pragma unroll
    for (int j = 0; j < 8; j++) acc[j] = 0ULL;
#pragma unroll 4
    for (int k = 0; k < 64; k++) {
        unsigned long long wp = splat2(W[k * 128 + ch]);
        const ulonglong2* row = reinterpret_cast<const ulonglong2*>(&sIn[k][half * 16]);
#pragma unroll
        for (int g = 0; g < 4; g++) {
            ulonglong2 v = row[g];
            ffma2(acc[2 * g], v.x, wp);
            ffma2(acc[2 * g + 1], v.y, wp);
        }
    }
    float bb = b[ch];
#pragma unroll
    for (int j = 0; j < 8; j++) {
        float lo, hi;
        unpack2(acc[j], lo, hi);
        int n0 = base + half * 16 + 2 * j;
        if (n0 < n)     out[n0 * 128 + ch]       = selu_f(lo + bb);
        if (n0 + 1 < n) out[(n0 + 1) * 128 + ch] = selu_f(hi + bb);
    }
}

#define GEMM128_CORE(OUTSTMT)                                                   \
    __syncthreads();                                                            \
    int ch = tid & 127, half = tid >> 7;                                        \
    unsigned long long acc[8];                                                  \
    _Pragma("unroll")                                                           \
    for (int j = 0; j < 8; j++) acc[j] = 0ULL;                                  \
    _Pragma("unroll 4")                                                         \
    for (int k = 0; k < 131; k++) {                                             \
        unsigned long long wp = splat2(W[k * 128 + ch]);                        \
        const ulonglong2* row = reinterpret_cast<const ulonglong2*>(&sIn[k][half * 16]); \
        _Pragma("unroll")                                                       \
        for (int g = 0; g < 4; g++) {                                           \
            ulonglong2 v = row[g];                                              \
            ffma2(acc[2 * g], v.x, wp);                                         \
            ffma2(acc[2 * g + 1], v.y, wp);                                     \
        }                                                                       \
    }                                                                           \
    float bb = b[ch];                                                           \
    _Pragma("unroll")                                                           \
    for (int j = 0; j < 8; j++) {                                               \
        float lo, hi;                                                           \
        unpack2(acc[j], lo, hi);                                                \
        int n0 = base + half * 16 + 2 * j;                                      \
        OUTSTMT                                                                 \
    }

__global__ void __launch_bounds__(256) gemm128_kernel(
    const float* __restrict__ x, const float* __restrict__ pos,
    const float* __restrict__ W, const float* __restrict__ dinv,
    const float* __restrict__ b, int n,
    float* __restrict__ xw, float* __restrict__ accout, int seluflag) {
    const int NT = 32;
    __shared__ __align__(16) float sIn[131][NT + 4];
    int base = blockIdx.x * NT;
    int tid = threadIdx.x;
    for (int i = tid; i < NT * 128; i += 256) {
        int r = i >> 7, c = i & 127;
        int node = base + r;
        float v = 0.f;
        if (node < n) {
            v = x[node * 128 + c];
            if (seluflag) v = selu_f(v);
        }
        sIn[c][r] = v;
    }
    for (int i = tid; i < NT * 3; i += 256) {
        int r = i / 3, c = i - r * 3;
        int node = base + r;
        sIn[128 + c][r] = (node < n) ? pos[node * 3 + c] : 0.f;
    }
    GEMM128_CORE(
        if (n0 < n) {
            float s = dinv[n0];
            xw[n0 * 128 + ch] = lo;
            accout[n0 * 128 + ch] = fmaf(lo, s * s, bb);
        }
        if (n0 + 1 < n) {
            float s = dinv[n0 + 1];
            xw[(n0 + 1) * 128 + ch] = hi;
            accout[(n0 + 1) * 128 + ch] = fmaf(hi, s * s, bb);
        }
    )
}

__global__ void __launch_bounds__(256) gemm128i_kernel(
    const float* __restrict__ xsrc, const int* __restrict__ idxArr,
    const float* __restrict__ d2Arr, const float* __restrict__ pos,
    const float* __restrict__ W, const float* __restrict__ dinv,
    const float* __restrict__ b, int n,
    float* __restrict__ xw, float* __restrict__ accout) {
    const int NT = 32;
    __shared__ __align__(16) float sIn[131][NT + 4];
    __shared__ int sI[NT][3];
    __shared__ float sWt[NT][4];
    int base = blockIdx.x * NT;
    int tid = threadIdx.x;
    if (tid < NT) {
        int node = base + tid;
        if (node < n) {
            float w0 = 1.0f / fmaxf(d2Arr[node * 3],     1e-16f);
            float w1 = 1.0f / fmaxf(d2Arr[node * 3 + 1], 1e-16f);
            float w2 = 1.0f / fmaxf(d2Arr[node * 3 + 2], 1e-16f);
            sI[tid][0] = idxArr[node * 3];
            sI[tid][1] = idxArr[node * 3 + 1];
            sI[tid][2] = idxArr[node * 3 + 2];
            sWt[tid][0] = w0; sWt[tid][1] = w1; sWt[tid][2] = w2;
            sWt[tid][3] = w0 + w1 + w2;
        } else {
            sI[tid][0] = sI[tid][1] = sI[tid][2] = 0;
            sWt[tid][0] = sWt[tid][1] = sWt[tid][2] = 0.f; sWt[tid][3] = 1.f;
        }
    }
    __syncthreads();
    for (int i = tid; i < NT * 128; i += 256) {
        int r = i >> 7, c = i & 127;
        int node = base + r;
        float v = 0.f;
        if (node < n) {
            float num = sWt[r][0] * selu_f(xsrc[sI[r][0] * 128 + c]);
            num = fmaf(sWt[r][1], selu_f(xsrc[sI[r][1] * 128 + c]), num);
            num = fmaf(sWt[r][2], selu_f(xsrc[sI[r][2] * 128 + c]), num);
            v = num / sWt[r][3];
        }
        sIn[c][r] = v;
    }
    for (int i = tid; i < NT * 3; i += 256) {
        int r = i / 3, c = i - r * 3;
        int node = base + r;
        sIn[128 + c][r] = (node < n) ? pos[node * 3 + c] : 0.f;
    }
    GEMM128_CORE(
        if (n0 < n) {
            float s = dinv[n0];
            xw[n0 * 128 + ch] = lo;
            accout[n0 * 128 + ch] = fmaf(lo, s * s, bb);
        }
        if (n0 + 1 < n) {
            float s = dinv[n0 + 1];
            xw[(n0 + 1) * 128 + ch] = hi;
            accout[(n0 + 1) * 128 + ch] = fmaf(hi, s * s, bb);
        }
    )
}

#define SCHUNK 16
__global__ void __launch_bounds__(256) scatterS128_kernel(
    const float4* __restrict__ xw4, const float* __restrict__ dinv,
    const int* __restrict__ srow, const int* __restrict__ scol,
    int E, float4* __restrict__ acc4) {
    int warp = (blockIdx.x * blockDim.x + threadIdx.x) >> 5;
    int j = threadIdx.x & 31;
    int base = warp * SCHUNK;
    if (base >= E) return;
    int end = min(base + SCHUNK, E);
    int cur = scol[base];
    float dc = dinv[cur];
    float4 acc = make_float4(0.f, 0.f, 0.f, 0.f);
    for (int t = base; t < end; t++) {
        int r = srow[t];
        int c = scol[t];
        if (c != cur) {
            red4((float*)&acc4[cur * 32 + j], acc);
            acc = make_float4(0.f, 0.f, 0.f, 0.f);
            cur = c;
            dc = dinv[c];
        }
        float nrm = dinv[r] * dc;
        float4 v = xw4[r * 32 + j];
        acc.x = fmaf(v.x, nrm, acc.x);
        acc.y = fmaf(v.y, nrm, acc.y);
        acc.z = fmaf(v.z, nrm, acc.z);
        acc.w = fmaf(v.w, nrm, acc.w);
    }
    red4((float*)&acc4[cur * 32 + j], acc);
}

__global__ void __launch_bounds__(128) gemm5_kernel(
    const float* __restrict__ x, const float* __restrict__ pos,
    const float* __restrict__ W, const float* __restrict__ dinv,
    const float* __restrict__ b, int n,
    float* __restrict__ xw, float* __restrict__ accout, int seluflag) {
    const int NT = 25;
    __shared__ float sIn[NT][132];
    __shared__ float sW[131 * 5];
    int tid = threadIdx.x;
    for (int i = tid; i < 131 * 5; i += 128) sW[i] = W[i];
    int base = blockIdx.x * NT;
    for (int i = tid; i < NT * 132; i += 128) {
        int r = i / 132, c = i - r * 132;
        int node = base + r;
        float v = 0.f;
        if (node < n && c < 131) {
            if (c < 128) {
                v = x[node * 128 + c];
                if (seluflag) v = selu_f(v);
            } else {
                v = pos[node * 3 + (c - 128)];
            }
        }
        sIn[r][c] = v;
    }
    __syncthreads();
    if (tid < 125) {
        int r = tid / 5, c = tid - r * 5;
        int node = base + r;
        if (node < n) {
            float acc = 0.f;
            for (int k = 0; k < 131; k++) acc = fmaf(sIn[r][k], sW[k * 5 + c], acc);
            float s = dinv[node];
            xw[node * 5 + c] = acc;
            accout[node * 5 + c] = fmaf(acc, s * s, b[c]);
        }
    }
}

__global__ void scatter5_kernel(const float* __restrict__ xw, const float* __restrict__ dinv,
                                const int* __restrict__ row, const int* __restrict__ col,
                                int E, float* __restrict__ acc) {
    int gid = blockIdx.x * blockDim.x + threadIdx.x;
    int e = gid / 5;
    int j = gid - e * 5;
    if (e >= E) return;
    int r = row[e], c = col[e];
    atomicAdd(&acc[c * 5 + j], xw[r * 5 + j] * dinv[r] * dinv[c]);
}

// ---------------- orchestration ----------------

static inline int cdiv(int a, int b) { return (a + b - 1) / b; }

extern "C" void kernel_launch(void* const* d_in, const int* in_sizes, int n_in,
                              void* d_out, int out_size) {
    const float* latent = (const float*)d_in[0];
    const float* pos0 = (const float*)d_in[1];
    const float* pos1 = (const float*)d_in[2];
    const float* pos2 = (const float*)d_in[3];
    const float* Wlin = (const float*)d_in[4];
    const float* blin = (const float*)d_in[5];
    const float* W0 = (const float*)d_in[6];  const float* b0 = (const float*)d_in[7];
    const float* W1 = (const float*)d_in[8];  const float* b1 = (const float*)d_in[9];
    const float* W2 = (const float*)d_in[10]; const float* b2 = (const float*)d_in[11];
    const float* W3 = (const float*)d_in[12]; const float* b3 = (const float*)d_in[13];
    const float* W4 = (const float*)d_in[14]; const float* b4 = (const float*)d_in[15];
    const int* e0 = (const int*)d_in[16];
    const int* e1 = (const int*)d_in[17];
    const int* e2 = (const int*)d_in[18];
    float* out = (float*)d_out;

    int N0 = in_sizes[1] / 3, N1 = in_sizes[2] / 3, N2 = in_sizes[3] / 3;
    int E0 = in_sizes[16] / 2, E1 = in_sizes[17] / 2, E2 = in_sizes[18] / 2;

    float *A, *B, *C, *dv0, *dv1, *dv2, *tp0, *tp1, *tp2, *d201, *d212;
    int *idx01, *idx12;
    unsigned *bb0, *bb1;
    GridParams *gp0, *gp1;
    int *cc0, *cs0, *cu0, *cc1, *cs1, *cu1;
    float4 *sp0, *sp1, *sq12;
    int *si0, *si1;
    int *ecnt, *ecur;
    int *sr0, *sc0, *sr1, *sc1, *sr2, *sc2;
    int *qc1, *qs1, *qu1, *qp12;
    cudaGetSymbolAddress((void**)&A, g_A);
    cudaGetSymbolAddress((void**)&B, g_B);
    cudaGetSymbolAddress((void**)&C, g_C);
    cudaGetSymbolAddress((void**)&dv0, g_dinv0);
    cudaGetSymbolAddress((void**)&dv1, g_dinv1);
    cudaGetSymbolAddress((void**)&dv2, g_dinv2);
    cudaGetSymbolAddress((void**)&tp0, g_tp0);
    cudaGetSymbolAddress((void**)&tp1, g_tp1);
    cudaGetSymbolAddress((void**)&tp2, g_tp2);
    cudaGetSymbolAddress((void**)&idx01, g_idx01);
    cudaGetSymbolAddress((void**)&d201, g_d201);
    cudaGetSymbolAddress((void**)&idx12, g_idx12);
    cudaGetSymbolAddress((void**)&d212, g_d212);
    cudaGetSymbolAddress((void**)&bb0, g_bbox0);
    cudaGetSymbolAddress((void**)&bb1, g_bbox1);
    cudaGetSymbolAddress((void**)&gp0, g_gp0);
    cudaGetSymbolAddress((void**)&gp1, g_gp1);
    cudaGetSymbolAddress((void**)&cc0, g_cellCnt0);
    cudaGetSymbolAddress((void**)&cs0, g_cellStart0);
    cudaGetSymbolAddress((void**)&cu0, g_cellCur0);
    cudaGetSymbolAddress((void**)&cc1, g_cellCnt1);
    cudaGetSymbolAddress((void**)&cs1, g_cellStart1);
    cudaGetSymbolAddress((void**)&cu1, g_cellCur1);
    cudaGetSymbolAddress((void**)&sp0, g_spts0);
    cudaGetSymbolAddress((void**)&si0, g_sidx0);
    cudaGetSymbolAddress((void**)&sp1, g_spts1);
    cudaGetSymbolAddress((void**)&si1, g_sidx1);
    cudaGetSymbolAddress((void**)&ecnt, g_ecnt);
    cudaGetSymbolAddress((void**)&ecur, g_ecur);
    cudaGetSymbolAddress((void**)&sr0, g_srow0);
    cudaGetSymbolAddress((void**)&sc0, g_scol0);
    cudaGetSymbolAddress((void**)&sr1, g_srow1);
    cudaGetSymbolAddress((void**)&sc1, g_scol1);
    cudaGetSymbolAddress((void**)&sr2, g_srow2);
    cudaGetSymbolAddress((void**)&sc2, g_scol2);
    cudaGetSymbolAddress((void**)&qc1, g_qCnt1);
    cudaGetSymbolAddress((void**)&qs1, g_qStart1);
    cudaGetSymbolAddress((void**)&qu1, g_qCur1);
    cudaGetSymbolAddress((void**)&sq12, g_sq12);
    cudaGetSymbolAddress((void**)&qp12, g_qperm12);

    static cudaStream_t sDeg = nullptr, sGeo0 = nullptr, sKnn2 = nullptr;
    static cudaEvent_t evStart, evT1, evS0, evS1, evS2, evK01, evK12,
                       evDegDone, evGeo0Done, evKnn2Done;
    if (!sDeg) {
        cudaStreamCreateWithFlags(&sDeg, cudaStreamNonBlocking);
        cudaStreamCreateWithFlags(&sGeo0, cudaStreamNonBlocking);
        cudaStreamCreateWithFlags(&sKnn2, cudaStreamNonBlocking);
        cudaEventCreateWithFlags(&evStart, cudaEventDisableTiming);
        cudaEventCreateWithFlags(&evT1, cudaEventDisableTiming);
        cudaEventCreateWithFlags(&evS0, cudaEventDisableTiming);
        cudaEventCreateWithFlags(&evS1, cudaEventDisableTiming);
        cudaEventCreateWithFlags(&evS2, cudaEventDisableTiming);
        cudaEventCreateWithFlags(&evK01, cudaEventDisableTiming);
        cudaEventCreateWithFlags(&evK12, cudaEventDisableTiming);
        cudaEventCreateWithFlags(&evDegDone, cudaEventDisableTiming);
        cudaEventCreateWithFlags(&evGeo0Done, cudaEventDisableTiming);
        cudaEventCreateWithFlags(&evKnn2Done, cudaEventDisableTiming);
    }

    // ---- fork ----
    cudaEventRecord(evStart, 0);
    cudaStreamWaitEvent(sDeg, evStart, 0);
    cudaStreamWaitEvent(sGeo0, evStart, 0);
    cudaStreamWaitEvent(sKnn2, evStart, 0);

    // ---- sKnn2: grid1 + sorted knn12 ASAP ----
    initbbox_kernel<<<1, 32, 0, sKnn2>>>(bb1);
    zero2_kernel<<<cdiv(MAXCELLS, 256), 256, 0, sKnn2>>>(cc1, qc1, MAXCELLS);
    transform_kernel<<<cdiv(N1, 256), 256, 0, sKnn2>>>(pos1, N1, tp1, bb1);
    cudaEventRecord(evT1, sKnn2);
    transform_kernel<<<cdiv(N2, 256), 256, 0, sKnn2>>>(pos2, N2, tp2, nullptr);
    gridparams_kernel<<<1, 32, 0, sKnn2>>>(bb1, N1, gp1);
    gridcount_kernel<<<cdiv(N1, 256), 256, 0, sKnn2>>>(tp1, N1, gp1, cc1);
    qcount_kernel<<<cdiv(N2, 256), 256, 0, sKnn2>>>(tp2, N2, gp1, qc1);
    scan_kernel<<<1, 1024, 0, sKnn2>>>(cc1, cs1, cu1);
    scan_kernel<<<1, 1024, 0, sKnn2>>>(qc1, qs1, qu1);
    gridscatter_kernel<<<cdiv(N1, 256), 256, 0, sKnn2>>>(tp1, N1, gp1, cu1, sp1, si1);
    qscatter_kernel<<<cdiv(N2, 256), 256, 0, sKnn2>>>(tp2, N2, gp1, qu1, sq12, qp12);
    gridknn_sorted_kernel<<<cdiv(N2, 128), 128, 0, sKnn2>>>(sq12, qp12, N2, gp1, cs1, sp1, si1, idx12, d212);
    cudaEventRecord(evK12, sKnn2);
    cudaEventRecord(evKnn2Done, sKnn2);

    // ---- sDeg: per-level edge sort + dinv ----
    zeroints_kernel<<<cdiv(N0, 256), 256, 0, sDeg>>>(ecnt, N0);
    countint_kernel<<<cdiv(E0, 256), 256, 0, sDeg>>>(e0 + E0, E0, ecnt);
    scanN_kernel<<<1, 1024, 0, sDeg>>>(ecnt, N0, ecur);
    dinvcnt_kernel<<<cdiv(N0, 256), 256, 0, sDeg>>>(ecnt, dv0, N0);
    sortfill_kernel<<<cdiv(E0, 256), 256, 0, sDeg>>>(e0, e0 + E0, E0, ecur, sr0, sc0);
    cudaEventRecord(evS0, sDeg);
    zeroints_kernel<<<cdiv(N1, 256), 256, 0, sDeg>>>(ecnt, N1);
    countint_kernel<<<cdiv(E1, 256), 256, 0, sDeg>>>(e1 + E1, E1, ecnt);
    scanN_kernel<<<1, 1024, 0, sDeg>>>(ecnt, N1, ecur);
    dinvcnt_kernel<<<cdiv(N1, 256), 256, 0, sDeg>>>(ecnt, dv1, N1);
    sortfill_kernel<<<cdiv(E1, 256), 256, 0, sDeg>>>(e1, e1 + E1, E1, ecur, sr1, sc1);
    cudaEventRecord(evS1, sDeg);
    zeroints_kernel<<<cdiv(N2, 256), 256, 0, sDeg>>>(ecnt, N2);
    countint_kernel<<<cdiv(E2, 256), 256, 0, sDeg>>>(e2 + E2, E2, ecnt);
    scanN_kernel<<<1, 1024, 0, sDeg>>>(ecnt, N2, ecur);
    dinvcnt_kernel<<<cdiv(N2, 256), 256, 0, sDeg>>>(ecnt, dv2, N2);
    sortfill_kernel<<<cdiv(E2, 256), 256, 0, sDeg>>>(e2, e2 + E2, E2, ecur, sr2, sc2);
    cudaEventRecord(evS2, sDeg);
    cudaEventRecord(evDegDone, sDeg);

    // ---- sGeo0: tp0 + grid0 + knn01 ----
    initbbox_kernel<<<1, 32, 0, sGeo0>>>(bb0);
    transform_kernel<<<cdiv(N0, 256), 256, 0, sGeo0>>>(pos0, N0, tp0, bb0);
    gridparams_kernel<<<1, 32, 0, sGeo0>>>(bb0, N0, gp0);
    zeroints_kernel<<<cdiv(MAXCELLS, 256), 256, 0, sGeo0>>>(cc0, MAXCELLS);
    gridcount_kernel<<<cdiv(N0, 256), 256, 0, sGeo0>>>(tp0, N0, gp0, cc0);
    scan_kernel<<<1, 1024, 0, sGeo0>>>(cc0, cs0, cu0);
    gridscatter_kernel<<<cdiv(N0, 256), 256, 0, sGeo0>>>(tp0, N0, gp0, cu0, sp0, si0);
    cudaStreamWaitEvent(sGeo0, evT1, 0);
    gridknn_kernel<<<cdiv(N1, 128), 128, 0, sGeo0>>>(tp1, N1, gp0, cs0, sp0, si0, idx01, d201);
    cudaEventRecord(evK01, sGeo0);
    cudaEventRecord(evGeo0Done, sGeo0);

    // ---- main stream ----
    linear_selu_kernel<<<cdiv(N0, 32), 256>>>(latent, Wlin, blin, N0, A);

    cudaStreamWaitEvent(0, evS0, 0);
    gemm128_kernel<<<cdiv(N0, 32), 256>>>(A, pos0, W0, dv0, b0, N0, B, C, 0);
    scatterS128_kernel<<<cdiv(cdiv(E0, SCHUNK) * 32, 256), 256>>>((const float4*)B, dv0, sr0, sc0, E0, (float4*)C);

    gemm128_kernel<<<cdiv(N0, 32), 256>>>(C, pos0, W1, dv0, b1, N0, B, A, 1);
    scatterS128_kernel<<<cdiv(cdiv(E0, SCHUNK) * 32, 256), 256>>>((const float4*)B, dv0, sr0, sc0, E0, (float4*)A);

    cudaStreamWaitEvent(0, evK01, 0);
    cudaStreamWaitEvent(0, evS1, 0);
    gemm128i_kernel<<<cdiv(N1, 32), 256>>>(A, idx01, d201, pos1, W2, dv1, b2, N1, B, C);
    scatterS128_kernel<<<cdiv(cdiv(E1, SCHUNK) * 32, 256), 256>>>((const float4*)B, dv1, sr1, sc1, E1, (float4*)C);

    cudaStreamWaitEvent(0, evK12, 0);
    cudaStreamWaitEvent(0, evS2, 0);
    gemm128i_kernel<<<cdiv(N2, 32), 256>>>(C, idx12, d212, pos2, W3, dv2, b3, N2, A, B);
    scatterS128_kernel<<<cdiv(cdiv(E2, SCHUNK) * 32, 256), 256>>>((const float4*)A, dv2, sr2, sc2, E2, (float4*)B);

    gemm5_kernel<<<cdiv(N2, 25), 128>>>(B, pos2, W4, dv2, b4, N2, C, out, 1);
    scatter5_kernel<<<cdiv(E2 * 5, 256), 256>>>(C, dv2, e2, e2 + E2, E2, out);

    // join
    cudaStreamWaitEvent(0, evDegDone, 0);
    cudaStreamWaitEvent(0, evGeo0Done, 0);
    cudaStreamWaitEvent(0, evKnn2Done, 0);
}

// round 17
// speedup vs baseline: 1.6357x; 1.6357x over previous
#include <cuda_runtime.h>
#include <math.h>

#define HC 128
#define N2MAX 96000
#define MAXCELLS 65536

// ---------------- scratch (static device globals; no allocation) ----------------
__device__ __align__(16) float g_A[N2MAX * HC];
__device__ __align__(16) float g_B[N2MAX * HC];
__device__ __align__(16) float g_C[N2MAX * HC];
__device__ float g_dinv0[16000];
__device__ float g_dinv1[32000];
__device__ float g_dinv2[96000];
__device__ float g_tp0[16000 * 3];
__device__ float g_tp1[32000 * 3];
__device__ float g_tp2[96000 * 3];
__device__ int   g_idx01[32000 * 3];
__device__ float g_d201[32000 * 3];
__device__ int   g_idx12[N2MAX * 3];
__device__ float g_d212[N2MAX * 3];

// edge sort scratch (built on side stream)
__device__ int g_ecnt[N2MAX];
__device__ int g_ecur[N2MAX];
__device__ int g_srow0[128000], g_scol0[128000];
__device__ int g_srow1[256000], g_scol1[256000];
__device__ int g_srow2[768000], g_scol2[768000];

// grid kNN scratch — separate per stage
struct GridParams { float ox, oy, oz, h, invh; int Gx, Gy, Gz, Rmax; };
__device__ unsigned g_bbox0[6];
__device__ unsigned g_bbox1[6];
__device__ GridParams g_gp0, g_gp1;
__device__ int g_cellCnt0[MAXCELLS], g_cellStart0[MAXCELLS + 1], g_cellCur0[MAXCELLS];
__device__ int g_cellCnt1[MAXCELLS], g_cellStart1[MAXCELLS + 1], g_cellCur1[MAXCELLS];
__device__ __align__(16) float4 g_spts0[16000];
__device__ int g_sidx0[16000];
__device__ __align__(16) float4 g_spts1[32000];
__device__ int g_sidx1[32000];

// ---------------- helpers ----------------
__device__ __forceinline__ unsigned fkey(float f) {
    unsigned u = __float_as_uint(f);
    return (u & 0x80000000u) ? ~u : (u | 0x80000000u);
}
__device__ __forceinline__ float fdec(unsigned k) {
    return (k & 0x80000000u) ? __uint_as_float(k ^ 0x80000000u) : __uint_as_float(~k);
}
__device__ __forceinline__ float selu_f(float v) {
    const float alpha = 1.6732632423543772f;
    const float scale = 1.0507009873554805f;
    return scale * (v > 0.f ? v : alpha * expm1f(v));
}
__device__ __forceinline__ void ffma2(unsigned long long& d, unsigned long long a, unsigned long long b) {
    asm("fma.rn.f32x2 %0, %1, %2, %0;" : "+l"(d) : "l"(a), "l"(b));
}
__device__ __forceinline__ unsigned long long splat2(float w) {
    unsigned long long r;
    asm("mov.b64 %0, {%1, %1};" : "=l"(r) : "f"(w));
    return r;
}
__device__ __forceinline__ void unpack2(unsigned long long v, float& lo, float& hi) {
    asm("mov.b64 {%0, %1}, %2;" : "=f"(lo), "=f"(hi) : "l"(v));
}
__device__ __forceinline__ void red4(float* dst, float4 v) {
    asm volatile("red.global.add.v4.f32 [%0], {%1,%2,%3,%4};"
                 :: "l"(dst), "f"(v.x), "f"(v.y), "f"(v.z), "f"(v.w) : "memory");
}

// ---------------- grid kNN ----------------

__global__ void initbbox_kernel(unsigned* bbox) {
    int i = threadIdx.x;
    if (i < 6) bbox[i] = (i < 3) ? 0xFFFFFFFFu : 0u;
}

__global__ void transform_kernel(const float* __restrict__ pos, int n,
                                 float* __restrict__ out, unsigned* bbox) {
    int i = blockIdx.x * blockDim.x + threadIdx.x;
    bool valid = (i < n);
    float x = 0.f, y = 0.f, z = 0.f;
    if (valid) { x = pos[3 * i]; y = pos[3 * i + 1]; z = pos[3 * i + 2]; }
    float nx = x - 0.57735026918962576f * y;
    float s = 1.0f + 0.78571428571428571f * (y / 1.1963f);
    float ox = nx * s, oy = y * s, oz = z * s;
    if (valid) { out[3 * i] = ox; out[3 * i + 1] = oy; out[3 * i + 2] = oz; }
    if (bbox) {
        unsigned kx = valid ? fkey(ox) : 0xFFFFFFFFu;
        unsigned ky = valid ? fkey(oy) : 0xFFFFFFFFu;
        unsigned kz = valid ? fkey(oz) : 0xFFFFFFFFu;
        unsigned mnx = __reduce_min_sync(0xFFFFFFFFu, kx);
        unsigned mny = __reduce_min_sync(0xFFFFFFFFu, ky);
        unsigned mnz = __reduce_min_sync(0xFFFFFFFFu, kz);
        unsigned mxx = __reduce_max_sync(0xFFFFFFFFu, valid ? kx : 0u);
        unsigned mxy = __reduce_max_sync(0xFFFFFFFFu, valid ? ky : 0u);
        unsigned mxz = __reduce_max_sync(0xFFFFFFFFu, valid ? kz : 0u);
        if ((threadIdx.x & 31) == 0) {
            atomicMin(&bbox[0], mnx); atomicMin(&bbox[1], mny); atomicMin(&bbox[2], mnz);
            atomicMax(&bbox[3], mxx); atomicMax(&bbox[4], mxy); atomicMax(&bbox[5], mxz);
        }
    }
}

__global__ void gridparams_kernel(const unsigned* __restrict__ bbox, int np, GridParams* gpout) {
    if (threadIdx.x != 0 || blockIdx.x != 0) return;
    float ox = fdec(bbox[0]), oy = fdec(bbox[1]), oz = fdec(bbox[2]);
    float mx = fdec(bbox[3]), my = fdec(bbox[4]), mz = fdec(bbox[5]);
    float ex = mx - ox, ey = my - oy, ez = mz - oz;
    float em = fmaxf(ex, fmaxf(ey, ez));
    float eps = 1e-4f * em + 1e-6f;
    ox -= eps; oy -= eps; oz -= eps;
    ex += 2.f * eps; ey += 2.f * eps; ez += 2.f * eps;
    int target = np / 2; if (target < 1) target = 1;
    float h = cbrtf(ex * ey * ez / (float)target);
    if (h < 1e-6f) h = 1e-6f;
    int Gx, Gy, Gz;
    for (int it = 0; it < 64; it++) {
        Gx = (int)(ex / h) + 1; Gy = (int)(ey / h) + 1; Gz = (int)(ez / h) + 1;
        if (Gx < 1) Gx = 1; if (Gy < 1) Gy = 1; if (Gz < 1) Gz = 1;
        long long prod = (long long)Gx * Gy * Gz;
        if (prod <= MAXCELLS) break;
        h *= 1.0905f;
    }
    GridParams gp;
    gp.ox = ox; gp.oy = oy; gp.oz = oz; gp.h = h; gp.invh = 1.0f / h;
    gp.Gx = Gx; gp.Gy = Gy; gp.Gz = Gz;
    gp.Rmax = max(Gx, max(Gy, Gz));
    *gpout = gp;
}

__global__ void zeroints_kernel(int* __restrict__ a, int n) {
    int i = blockIdx.x * blockDim.x + threadIdx.x;
    if (i < n) a[i] = 0;
}

__device__ __forceinline__ int cell_of(float x, float y, float z, const GridParams& gp) {
    int cx = (int)floorf((x - gp.ox) * gp.invh);
    int cy = (int)floorf((y - gp.oy) * gp.invh);
    int cz = (int)floorf((z - gp.oz) * gp.invh);
    cx = min(max(cx, 0), gp.Gx - 1);
    cy = min(max(cy, 0), gp.Gy - 1);
    cz = min(max(cz, 0), gp.Gz - 1);
    return (cz * gp.Gy + cy) * gp.Gx + cx;
}

__global__ void gridcount_kernel(const float* __restrict__ p, int np,
                                 const GridParams* __restrict__ gpp, int* __restrict__ cnt) {
    int i = blockIdx.x * blockDim.x + threadIdx.x;
    if (i >= np) return;
    GridParams gp = *gpp;
    int c = cell_of(p[3 * i], p[3 * i + 1], p[3 * i + 2], gp);
    atomicAdd(&cnt[c], 1);
}

__global__ void __launch_bounds__(1024) scan_kernel(const int* __restrict__ cnt,
                                                    int* __restrict__ start,
                                                    int* __restrict__ cur) {
    __shared__ int ssum[1024];
    int tid = threadIdx.x;
    const int PER = MAXCELLS / 1024;
    int base = tid * PER;
    int sum = 0;
    for (int i = 0; i < PER; i++) sum += cnt[base + i];
    ssum[tid] = sum;
    __syncthreads();
    for (int off = 1; off < 1024; off <<= 1) {
        int v = (tid >= off) ? ssum[tid - off] : 0;
        __syncthreads();
        ssum[tid] += v;
        __syncthreads();
    }
    int run = ssum[tid] - sum;
    for (int i = 0; i < PER; i++) {
        start[base + i] = run;
        cur[base + i] = run;
        run += cnt[base + i];
    }
    if (tid == 1023) start[MAXCELLS] = run;
}

__global__ void gridscatter_kernel(const float* __restrict__ p, int np,
                                   const GridParams* __restrict__ gpp, int* __restrict__ cur,
                                   float4* __restrict__ spts, int* __restrict__ sidx) {
    int i = blockIdx.x * blockDim.x + threadIdx.x;
    if (i >= np) return;
    GridParams gp = *gpp;
    float x = p[3 * i], y = p[3 * i + 1], z = p[3 * i + 2];
    int c = cell_of(x, y, z, gp);
    int pos = atomicAdd(&cur[c], 1);
    float p2 = x * x;
    p2 = fmaf(y, y, p2);
    p2 = fmaf(z, z, p2);
    spts[pos] = make_float4(x, y, z, p2);
    sidx[pos] = i;
}

#define KNN_SCAN_SPAN(S_, E_)                                                   \
    for (int j_ = (S_); j_ < (E_); j_++) {                                      \
        float4 pt = spts[j_];                                                   \
        float dot = qx * pt.x;                                                  \
        dot = fmaf(qy, pt.y, dot);                                              \
        dot = fmaf(qz, pt.z, dot);                                              \
        float d = fmaf(-2.0f, dot, qq) + pt.w;                                  \
        if (d < b2) {                                                           \
            int gi = sidx[j_];                                                  \
            if (d < b0)      { b2 = b1; i2 = i1; b1 = b0; i1 = i0; b0 = d; i0 = gi; } \
            else if (d < b1) { b2 = b1; i2 = i1; b1 = d; i1 = gi; }             \
            else             { b2 = d; i2 = gi; }                               \
        }                                                                       \
    }

__global__ void __launch_bounds__(128) gridknn_kernel(
    const float* __restrict__ q, int nq,
    const GridParams* __restrict__ gpp, const int* __restrict__ cellStart,
    const float4* __restrict__ spts, const int* __restrict__ sidx,
    int* __restrict__ oidx, float* __restrict__ od2) {
    int qi = blockIdx.x * blockDim.x + threadIdx.x;
    if (qi >= nq) return;
    GridParams gp = *gpp;
    float qx = q[3 * qi], qy = q[3 * qi + 1], qz = q[3 * qi + 2];
    float qq = qx * qx;
    qq = fmaf(qy, qy, qq);
    qq = fmaf(qz, qz, qq);
    int ccx = (int)floorf((qx - gp.ox) * gp.invh);
    int ccy = (int)floorf((qy - gp.oy) * gp.invh);
    int ccz = (int)floorf((qz - gp.oz) * gp.invh);
    ccx = min(max(ccx, 0), gp.Gx - 1);
    ccy = min(max(ccy, 0), gp.Gy - 1);
    ccz = min(max(ccz, 0), gp.Gz - 1);

    float b0 = 1e30f, b1 = 1e30f, b2 = 1e30f;
    int i0 = 0, i1 = 0, i2 = 0;

    {
        int c = (ccz * gp.Gy + ccy) * gp.Gx + ccx;
        int s = cellStart[c], e = cellStart[c + 1];
        KNN_SCAN_SPAN(s, e);
    }
    for (int r = 1; r <= gp.Rmax; r++) {
        float dm = (float)(r - 1) * gp.h;
        if (b2 <= dm * dm) break;
        for (int dz = -r; dz <= r; dz++) {
            int z = ccz + dz;
            if (z < 0 || z >= gp.Gz) continue;
            bool zface = (dz == -r) || (dz == r);
            for (int dy = -r; dy <= r; dy++) {
                int y = ccy + dy;
                if (y < 0 || y >= gp.Gy) continue;
                bool face = zface || (dy == -r) || (dy == r);
                int rowbase = (z * gp.Gy + y) * gp.Gx;
                if (face) {
                    int x0 = max(ccx - r, 0), x1 = min(ccx + r, gp.Gx - 1);
                    int s = cellStart[rowbase + x0], e = cellStart[rowbase + x1 + 1];
                    KNN_SCAN_SPAN(s, e);
                } else {
                    int x = ccx - r;
                    if (x >= 0) {
                        int s = cellStart[rowbase + x], e = cellStart[rowbase + x + 1];
                        KNN_SCAN_SPAN(s, e);
                    }
                    x = ccx + r;
                    if (x < gp.Gx) {
                        int s = cellStart[rowbase + x], e = cellStart[rowbase + x + 1];
                        KNN_SCAN_SPAN(s, e);
                    }
                }
            }
        }
    }
    oidx[qi * 3] = i0; oidx[qi * 3 + 1] = i1; oidx[qi * 3 + 2] = i2;
    od2[qi * 3] = b0;  od2[qi * 3 + 1] = b1;  od2[qi * 3 + 2] = b2;
}

// ---------------- edge sort (counting sort by col) + dinv ----------------

__global__ void countint_kernel(const int* __restrict__ col, int E, int* __restrict__ cnt) {
    int e = blockIdx.x * blockDim.x + threadIdx.x;
    if (e < E) atomicAdd(&cnt[col[e]], 1);
}

__global__ void __launch_bounds__(1024) scanN_kernel(const int* __restrict__ cnt, int n,
                                                     int* __restrict__ cur) {
    __shared__ int ssum[1024];
    int tid = threadIdx.x;
    int per = (n + 1023) >> 10;
    int base = tid * per;
    int sum = 0;
    for (int i = 0; i < per; i++) {
        int c = base + i;
        if (c < n) sum += cnt[c];
    }
    ssum[tid] = sum;
    __syncthreads();
    for (int off = 1; off < 1024; off <<= 1) {
        int v = (tid >= off) ? ssum[tid - off] : 0;
        __syncthreads();
        ssum[tid] += v;
        __syncthreads();
    }
    int run = ssum[tid] - sum;
    for (int i = 0; i < per; i++) {
        int c = base + i;
        if (c < n) { cur[c] = run; run += cnt[c]; }
    }
}

__global__ void dinvcnt_kernel(const int* __restrict__ cnt, float* __restrict__ d, int n) {
    int i = blockIdx.x * blockDim.x + threadIdx.x;
    if (i < n) d[i] = rsqrtf((float)cnt[i] + 1.0f);
}

__global__ void sortfill_kernel(const int* __restrict__ row, const int* __restrict__ col, int E,
                                int* __restrict__ cur, int* __restrict__ srow, int* __restrict__ scol) {
    int e = blockIdx.x * blockDim.x + threadIdx.x;
    if (e >= E) return;
    int c = col[e];
    int p = atomicAdd(&cur[c], 1);
    srow[p] = row[e];
    scol[p] = c;
}

// ---------------- dense ops (FFMA2) ----------------

__global__ void __launch_bounds__(256) linear_selu_kernel(
    const float* __restrict__ latent, const float* __restrict__ W,
    const float* __restrict__ b, int n, float* __restrict__ out) {
    const int NT = 32;
    __shared__ __align__(16) float sIn[64][NT + 4];
    int base = blockIdx.x * NT;
    int tid = threadIdx.x;
    for (int i = tid; i < NT * 64; i += 256) {
        int r = i >> 6, c = i & 63;
        int node = base + r;
        sIn[c][r] = (node < n) ? latent[node * 64 + c] : 0.f;
    }
    __syncthreads();
    int ch = tid & 127, half = tid >> 7;
    unsigned long long acc[8];
#pragma unroll
    for (int j = 0; j < 8; j++) acc[j] = 0ULL;
#pragma unroll 4
    for (int k = 0; k < 64; k++) {
        unsigned long long wp = splat2(W[k * 128 + ch]);
        const ulonglong2* row = reinterpret_cast<const ulonglong2*>(&sIn[k][half * 16]);
#pragma unroll
        for (int g = 0; g < 4; g++) {
            ulonglong2 v = row[g];
            ffma2(acc[2 * g], v.x, wp);
            ffma2(acc[2 * g + 1], v.y, wp);
        }
    }
    float bb = b[ch];
#pragma unroll
    for (int j = 0; j < 8; j++) {
        float lo, hi;
        unpack2(acc[j], lo, hi);
        int n0 = base + half * 16 + 2 * j;
        if (n0 < n)     out[n0 * 128 + ch]       = selu_f(lo + bb);
        if (n0 + 1 < n) out[(n0 + 1) * 128 + ch] = selu_f(hi + bb);
    }
}

#define GEMM128_CORE(OUTSTMT)                                                   \
    __syncthreads();                                                            \
    int ch = tid & 127, half = tid >> 7;                                        \
    unsigned long long acc[8];                                                  \
    _Pragma("unroll")                                                           \
    for (int j = 0; j < 8; j++) acc[j] = 0ULL;                                  \
    _Pragma("unroll 4")                                                         \
    for (int k = 0; k < 131; k++) {                                             \
        unsigned long long wp = splat2(W[k * 128 + ch]);                        \
        const ulonglong2* row = reinterpret_cast<const ulonglong2*>(&sIn[k][half * 16]); \
        _Pragma("unroll")                                                       \
        for (int g = 0; g < 4; g++) {                                           \
            ulonglong2 v = row[g];                                              \
            ffma2(acc[2 * g], v.x, wp);                                         \
            ffma2(acc[2 * g + 1], v.y, wp);                                     \
        }                                                                       \
    }                                                                           \
    float bb = b[ch];                                                           \
    _Pragma("unroll")                                                           \
    for (int j = 0; j < 8; j++) {                                               \
        float lo, hi;                                                           \
        unpack2(acc[j], lo, hi);                                                \
        int n0 = base + half * 16 + 2 * j;                                      \
        OUTSTMT                                                                 \
    }

__global__ void __launch_bounds__(256) gemm128_kernel(
    const float* __restrict__ x, const float* __restrict__ pos,
    const float* __restrict__ W, const float* __restrict__ dinv,
    const float* __restrict__ b, int n,
    float* __restrict__ xw, float* __restrict__ accout, int seluflag) {
    const int NT = 32;
    __shared__ __align__(16) float sIn[131][NT + 4];
    int base = blockIdx.x * NT;
    int tid = threadIdx.x;
    for (int i = tid; i < NT * 128; i += 256) {
        int r = i >> 7, c = i & 127;
        int node = base + r;
        float v = 0.f;
        if (node < n) {
            v = x[node * 128 + c];
            if (seluflag) v = selu_f(v);
        }
        sIn[c][r] = v;
    }
    for (int i = tid; i < NT * 3; i += 256) {
        int r = i / 3, c = i - r * 3;
        int node = base + r;
        sIn[128 + c][r] = (node < n) ? pos[node * 3 + c] : 0.f;
    }
    GEMM128_CORE(
        if (n0 < n) {
            float s = dinv[n0];
            xw[n0 * 128 + ch] = lo;
            accout[n0 * 128 + ch] = fmaf(lo, s * s, bb);
        }
        if (n0 + 1 < n) {
            float s = dinv[n0 + 1];
            xw[(n0 + 1) * 128 + ch] = hi;
            accout[(n0 + 1) * 128 + ch] = fmaf(hi, s * s, bb);
        }
    )
}

__global__ void __launch_bounds__(256) gemm128i_kernel(
    const float* __restrict__ xsrc, const int* __restrict__ idxArr,
    const float* __restrict__ d2Arr, const float* __restrict__ pos,
    const float* __restrict__ W, const float* __restrict__ dinv,
    const float* __restrict__ b, int n,
    float* __restrict__ xw, float* __restrict__ accout) {
    const int NT = 32;
    __shared__ __align__(16) float sIn[131][NT + 4];
    __shared__ int sI[NT][3];
    __shared__ float sWt[NT][4];
    int base = blockIdx.x * NT;
    int tid = threadIdx.x;
    if (tid < NT) {
        int node = base + tid;
        if (node < n) {
            float w0 = 1.0f / fmaxf(d2Arr[node * 3],     1e-16f);
            float w1 = 1.0f / fmaxf(d2Arr[node * 3 + 1], 1e-16f);
            float w2 = 1.0f / fmaxf(d2Arr[node * 3 + 2], 1e-16f);
            sI[tid][0] = idxArr[node * 3];
            sI[tid][1] = idxArr[node * 3 + 1];
            sI[tid][2] = idxArr[node * 3 + 2];
            sWt[tid][0] = w0; sWt[tid][1] = w1; sWt[tid][2] = w2;
            sWt[tid][3] = w0 + w1 + w2;
        } else {
            sI[tid][0] = sI[tid][1] = sI[tid][2] = 0;
            sWt[tid][0] = sWt[tid][1] = sWt[tid][2] = 0.f; sWt[tid][3] = 1.f;
        }
    }
    __syncthreads();
    for (int i = tid; i < NT * 128; i += 256) {
        int r = i >> 7, c = i & 127;
        int node = base + r;
        float v = 0.f;
        if (node < n) {
            float num = sWt[r][0] * selu_f(xsrc[sI[r][0] * 128 + c]);
            num = fmaf(sWt[r][1], selu_f(xsrc[sI[r][1] * 128 + c]), num);
            num = fmaf(sWt[r][2], selu_f(xsrc[sI[r][2] * 128 + c]), num);
            v = num / sWt[r][3];
        }
        sIn[c][r] = v;
    }
    for (int i = tid; i < NT * 3; i += 256) {
        int r = i / 3, c = i - r * 3;
        int node = base + r;
        sIn[128 + c][r] = (node < n) ? pos[node * 3 + c] : 0.f;
    }
    GEMM128_CORE(
        if (n0 < n) {
            float s = dinv[n0];
            xw[n0 * 128 + ch] = lo;
            accout[n0 * 128 + ch] = fmaf(lo, s * s, bb);
        }
        if (n0 + 1 < n) {
            float s = dinv[n0 + 1];
            xw[(n0 + 1) * 128 + ch] = hi;
            accout[(n0 + 1) * 128 + ch] = fmaf(hi, s * s, bb);
        }
    )
}

#define SCHUNK 16
__global__ void __launch_bounds__(256) scatterS128_kernel(
    const float4* __restrict__ xw4, const float* __restrict__ dinv,
    const int* __restrict__ srow, const int* __restrict__ scol,
    int E, float4* __restrict__ acc4) {
    int warp = (blockIdx.x * blockDim.x + threadIdx.x) >> 5;
    int j = threadIdx.x & 31;
    int base = warp * SCHUNK;
    if (base >= E) return;
    int end = min(base + SCHUNK, E);
    int cur = scol[base];
    float dc = dinv[cur];
    float4 acc = make_float4(0.f, 0.f, 0.f, 0.f);
    for (int t = base; t < end; t++) {
        int r = srow[t];
        int c = scol[t];
        if (c != cur) {
            red4((float*)&acc4[cur * 32 + j], acc);
            acc = make_float4(0.f, 0.f, 0.f, 0.f);
            cur = c;
            dc = dinv[c];
        }
        float nrm = dinv[r] * dc;
        float4 v = xw4[r * 32 + j];
        acc.x = fmaf(v.x, nrm, acc.x);
        acc.y = fmaf(v.y, nrm, acc.y);
        acc.z = fmaf(v.z, nrm, acc.z);
        acc.w = fmaf(v.w, nrm, acc.w);
    }
    red4((float*)&acc4[cur * 32 + j], acc);
}

__global__ void __launch_bounds__(128) gemm5_kernel(
    const float* __restrict__ x, const float* __restrict__ pos,
    const float* __restrict__ W, const float* __restrict__ dinv,
    const float* __restrict__ b, int n,
    float* __restrict__ xw, float* __restrict__ accout, int seluflag) {
    const int NT = 25;
    __shared__ float sIn[NT][132];
    __shared__ float sW[131 * 5];
    int tid = threadIdx.x;
    for (int i = tid; i < 131 * 5; i += 128) sW[i] = W[i];
    int base = blockIdx.x * NT;
    for (int i = tid; i < NT * 132; i += 128) {
        int r = i / 132, c = i - r * 132;
        int node = base + r;
        float v = 0.f;
        if (node < n && c < 131) {
            if (c < 128) {
                v = x[node * 128 + c];
                if (seluflag) v = selu_f(v);
            } else {
                v = pos[node * 3 + (c - 128)];
            }
        }
        sIn[r][c] = v;
    }
    __syncthreads();
    if (tid < 125) {
        int r = tid / 5, c = tid - r * 5;
        int node = base + r;
        if (node < n) {
            float acc = 0.f;
            for (int k = 0; k < 131; k++) acc = fmaf(sIn[r][k], sW[k * 5 + c], acc);
            float s = dinv[node];
            xw[node * 5 + c] = acc;
            accout[node * 5 + c] = fmaf(acc, s * s, b[c]);
        }
    }
}

// sorted-edge aggregated 5-ch scatter: one thread walks SCHUNK col-sorted edges,
// 5-ch run accumulation in registers, 5 atomics per run boundary.
__global__ void scatterS5_kernel(const float* __restrict__ xw, const float* __restrict__ dinv,
                                 const int* __restrict__ srow, const int* __restrict__ scol,
                                 int E, float* __restrict__ acc) {
    int t0 = (blockIdx.x * blockDim.x + threadIdx.x) * SCHUNK;
    if (t0 >= E) return;
    int end = min(t0 + SCHUNK, E);
    int cur = scol[t0];
    float dc = dinv[cur];
    float a0 = 0.f, a1 = 0.f, a2 = 0.f, a3 = 0.f, a4 = 0.f;
    for (int t = t0; t < end; t++) {
        int r = srow[t];
        int c = scol[t];
        if (c != cur) {
            atomicAdd(&acc[cur * 5 + 0], a0);
            atomicAdd(&acc[cur * 5 + 1], a1);
            atomicAdd(&acc[cur * 5 + 2], a2);
            atomicAdd(&acc[cur * 5 + 3], a3);
            atomicAdd(&acc[cur * 5 + 4], a4);
            a0 = a1 = a2 = a3 = a4 = 0.f;
            cur = c;
            dc = dinv[c];
        }
        float nrm = dinv[r] * dc;
        a0 = fmaf(xw[r * 5 + 0], nrm, a0);
        a1 = fmaf(xw[r * 5 + 1], nrm, a1);
        a2 = fmaf(xw[r * 5 + 2], nrm, a2);
        a3 = fmaf(xw[r * 5 + 3], nrm, a3);
        a4 = fmaf(xw[r * 5 + 4], nrm, a4);
    }
    atomicAdd(&acc[cur * 5 + 0], a0);
    atomicAdd(&acc[cur * 5 + 1], a1);
    atomicAdd(&acc[cur * 5 + 2], a2);
    atomicAdd(&acc[cur * 5 + 3], a3);
    atomicAdd(&acc[cur * 5 + 4], a4);
}

// ---------------- orchestration ----------------

static inline int cdiv(int a, int b) { return (a + b - 1) / b; }

extern "C" void kernel_launch(void* const* d_in, const int* in_sizes, int n_in,
                              void* d_out, int out_size) {
    const float* latent = (const float*)d_in[0];
    const float* pos0 = (const float*)d_in[1];
    const float* pos1 = (const float*)d_in[2];
    const float* pos2 = (const float*)d_in[3];
    const float* Wlin = (const float*)d_in[4];
    const float* blin = (const float*)d_in[5];
    const float* W0 = (const float*)d_in[6];  const float* b0 = (const float*)d_in[7];
    const float* W1 = (const float*)d_in[8];  const float* b1 = (const float*)d_in[9];
    const float* W2 = (const float*)d_in[10]; const float* b2 = (const float*)d_in[11];
    const float* W3 = (const float*)d_in[12]; const float* b3 = (const float*)d_in[13];
    const float* W4 = (const float*)d_in[14]; const float* b4 = (const float*)d_in[15];
    const int* e0 = (const int*)d_in[16];
    const int* e1 = (const int*)d_in[17];
    const int* e2 = (const int*)d_in[18];
    float* out = (float*)d_out;

    int N0 = in_sizes[1] / 3, N1 = in_sizes[2] / 3, N2 = in_sizes[3] / 3;
    int E0 = in_sizes[16] / 2, E1 = in_sizes[17] / 2, E2 = in_sizes[18] / 2;

    float *A, *B, *C, *dv0, *dv1, *dv2, *tp0, *tp1, *tp2, *d201, *d212;
    int *idx01, *idx12;
    unsigned *bb0, *bb1;
    GridParams *gp0, *gp1;
    int *cc0, *cs0, *cu0, *cc1, *cs1, *cu1;
    float4 *sp0, *sp1;
    int *si0, *si1;
    int *ecnt, *ecur;
    int *sr0, *sc0, *sr1, *sc1, *sr2, *sc2;
    cudaGetSymbolAddress((void**)&A, g_A);
    cudaGetSymbolAddress((void**)&B, g_B);
    cudaGetSymbolAddress((void**)&C, g_C);
    cudaGetSymbolAddress((void**)&dv0, g_dinv0);
    cudaGetSymbolAddress((void**)&dv1, g_dinv1);
    cudaGetSymbolAddress((void**)&dv2, g_dinv2);
    cudaGetSymbolAddress((void**)&tp0, g_tp0);
    cudaGetSymbolAddress((void**)&tp1, g_tp1);
    cudaGetSymbolAddress((void**)&tp2, g_tp2);
    cudaGetSymbolAddress((void**)&idx01, g_idx01);
    cudaGetSymbolAddress((void**)&d201, g_d201);
    cudaGetSymbolAddress((void**)&idx12, g_idx12);
    cudaGetSymbolAddress((void**)&d212, g_d212);
    cudaGetSymbolAddress((void**)&bb0, g_bbox0);
    cudaGetSymbolAddress((void**)&bb1, g_bbox1);
    cudaGetSymbolAddress((void**)&gp0, g_gp0);
    cudaGetSymbolAddress((void**)&gp1, g_gp1);
    cudaGetSymbolAddress((void**)&cc0, g_cellCnt0);
    cudaGetSymbolAddress((void**)&cs0, g_cellStart0);
    cudaGetSymbolAddress((void**)&cu0, g_cellCur0);
    cudaGetSymbolAddress((void**)&cc1, g_cellCnt1);
    cudaGetSymbolAddress((void**)&cs1, g_cellStart1);
    cudaGetSymbolAddress((void**)&cu1, g_cellCur1);
    cudaGetSymbolAddress((void**)&sp0, g_spts0);
    cudaGetSymbolAddress((void**)&si0, g_sidx0);
    cudaGetSymbolAddress((void**)&sp1, g_spts1);
    cudaGetSymbolAddress((void**)&si1, g_sidx1);
    cudaGetSymbolAddress((void**)&ecnt, g_ecnt);
    cudaGetSymbolAddress((void**)&ecur, g_ecur);
    cudaGetSymbolAddress((void**)&sr0, g_srow0);
    cudaGetSymbolAddress((void**)&sc0, g_scol0);
    cudaGetSymbolAddress((void**)&sr1, g_srow1);
    cudaGetSymbolAddress((void**)&sc1, g_scol1);
    cudaGetSymbolAddress((void**)&sr2, g_srow2);
    cudaGetSymbolAddress((void**)&sc2, g_scol2);

    static cudaStream_t sDeg = nullptr, sGeo0 = nullptr, sKnn2 = nullptr;
    static cudaEvent_t evStart, evT1, evS0, evS1, evS2, evK01, evK12,
                       evDegDone, evGeo0Done, evKnn2Done;
    if (!sDeg) {
        cudaStreamCreateWithFlags(&sDeg, cudaStreamNonBlocking);
        cudaStreamCreateWithFlags(&sGeo0, cudaStreamNonBlocking);
        cudaStreamCreateWithFlags(&sKnn2, cudaStreamNonBlocking);
        cudaEventCreateWithFlags(&evStart, cudaEventDisableTiming);
        cudaEventCreateWithFlags(&evT1, cudaEventDisableTiming);
        cudaEventCreateWithFlags(&evS0, cudaEventDisableTiming);
        cudaEventCreateWithFlags(&evS1, cudaEventDisableTiming);
        cudaEventCreateWithFlags(&evS2, cudaEventDisableTiming);
        cudaEventCreateWithFlags(&evK01, cudaEventDisableTiming);
        cudaEventCreateWithFlags(&evK12, cudaEventDisableTiming);
        cudaEventCreateWithFlags(&evDegDone, cudaEventDisableTiming);
        cudaEventCreateWithFlags(&evGeo0Done, cudaEventDisableTiming);
        cudaEventCreateWithFlags(&evKnn2Done, cudaEventDisableTiming);
    }

    // ---- fork ----
    cudaEventRecord(evStart, 0);
    cudaStreamWaitEvent(sDeg, evStart, 0);
    cudaStreamWaitEvent(sGeo0, evStart, 0);
    cudaStreamWaitEvent(sKnn2, evStart, 0);

    // ---- sKnn2: grid1 + knn12 ASAP (unsorted queries — binning is falsified) ----
    initbbox_kernel<<<1, 32, 0, sKnn2>>>(bb1);
    transform_kernel<<<cdiv(N1, 256), 256, 0, sKnn2>>>(pos1, N1, tp1, bb1);
    cudaEventRecord(evT1, sKnn2);
    transform_kernel<<<cdiv(N2, 256), 256, 0, sKnn2>>>(pos2, N2, tp2, nullptr);
    gridparams_kernel<<<1, 32, 0, sKnn2>>>(bb1, N1, gp1);
    zeroints_kernel<<<cdiv(MAXCELLS, 256), 256, 0, sKnn2>>>(cc1, MAXCELLS);
    gridcount_kernel<<<cdiv(N1, 256), 256, 0, sKnn2>>>(tp1, N1, gp1, cc1);
    scan_kernel<<<1, 1024, 0, sKnn2>>>(cc1, cs1, cu1);
    gridscatter_kernel<<<cdiv(N1, 256), 256, 0, sKnn2>>>(tp1, N1, gp1, cu1, sp1, si1);
    gridknn_kernel<<<cdiv(N2, 128), 128, 0, sKnn2>>>(tp2, N2, gp1, cs1, sp1, si1, idx12, d212);
    cudaEventRecord(evK12, sKnn2);
    cudaEventRecord(evKnn2Done, sKnn2);

    // ---- sDeg: per-level edge sort + dinv ----
    zeroints_kernel<<<cdiv(N0, 256), 256, 0, sDeg>>>(ecnt, N0);
    countint_kernel<<<cdiv(E0, 256), 256, 0, sDeg>>>(e0 + E0, E0, ecnt);
    scanN_kernel<<<1, 1024, 0, sDeg>>>(ecnt, N0, ecur);
    dinvcnt_kernel<<<cdiv(N0, 256), 256, 0, sDeg>>>(ecnt, dv0, N0);
    sortfill_kernel<<<cdiv(E0, 256), 256, 0, sDeg>>>(e0, e0 + E0, E0, ecur, sr0, sc0);
    cudaEventRecord(evS0, sDeg);
    zeroints_kernel<<<cdiv(N1, 256), 256, 0, sDeg>>>(ecnt, N1);
    countint_kernel<<<cdiv(E1, 256), 256, 0, sDeg>>>(e1 + E1, E1, ecnt);
    scanN_kernel<<<1, 1024, 0, sDeg>>>(ecnt, N1, ecur);
    dinvcnt_kernel<<<cdiv(N1, 256), 256, 0, sDeg>>>(ecnt, dv1, N1);
    sortfill_kernel<<<cdiv(E1, 256), 256, 0, sDeg>>>(e1, e1 + E1, E1, ecur, sr1, sc1);
    cudaEventRecord(evS1, sDeg);
    zeroints_kernel<<<cdiv(N2, 256), 256, 0, sDeg>>>(ecnt, N2);
    countint_kernel<<<cdiv(E2, 256), 256, 0, sDeg>>>(e2 + E2, E2, ecnt);
    scanN_kernel<<<1, 1024, 0, sDeg>>>(ecnt, N2, ecur);
    dinvcnt_kernel<<<cdiv(N2, 256), 256, 0, sDeg>>>(ecnt, dv2, N2);
    sortfill_kernel<<<cdiv(E2, 256), 256, 0, sDeg>>>(e2, e2 + E2, E2, ecur, sr2, sc2);
    cudaEventRecord(evS2, sDeg);
    cudaEventRecord(evDegDone, sDeg);

    // ---- sGeo0: tp0 + grid0 + knn01 ----
    initbbox_kernel<<<1, 32, 0, sGeo0>>>(bb0);
    transform_kernel<<<cdiv(N0, 256), 256, 0, sGeo0>>>(pos0, N0, tp0, bb0);
    gridparams_kernel<<<1, 32, 0, sGeo0>>>(bb0, N0, gp0);
    zeroints_kernel<<<cdiv(MAXCELLS, 256), 256, 0, sGeo0>>>(cc0, MAXCELLS);
    gridcount_kernel<<<cdiv(N0, 256), 256, 0, sGeo0>>>(tp0, N0, gp0, cc0);
    scan_kernel<<<1, 1024, 0, sGeo0>>>(cc0, cs0, cu0);
    gridscatter_kernel<<<cdiv(N0, 256), 256, 0, sGeo0>>>(tp0, N0, gp0, cu0, sp0, si0);
    cudaStreamWaitEvent(sGeo0, evT1, 0);
    gridknn_kernel<<<cdiv(N1, 128), 128, 0, sGeo0>>>(tp1, N1, gp0, cs0, sp0, si0, idx01, d201);
    cudaEventRecord(evK01, sGeo0);
    cudaEventRecord(evGeo0Done, sGeo0);

    // ---- main stream ----
    linear_selu_kernel<<<cdiv(N0, 32), 256>>>(latent, Wlin, blin, N0, A);

    cudaStreamWaitEvent(0, evS0, 0);
    gemm128_kernel<<<cdiv(N0, 32), 256>>>(A, pos0, W0, dv0, b0, N0, B, C, 0);
    scatterS128_kernel<<<cdiv(cdiv(E0, SCHUNK) * 32, 256), 256>>>((const float4*)B, dv0, sr0, sc0, E0, (float4*)C);

    gemm128_kernel<<<cdiv(N0, 32), 256>>>(C, pos0, W1, dv0, b1, N0, B, A, 1);
    scatterS128_kernel<<<cdiv(cdiv(E0, SCHUNK) * 32, 256), 256>>>((const float4*)B, dv0, sr0, sc0, E0, (float4*)A);

    cudaStreamWaitEvent(0, evK01, 0);
    cudaStreamWaitEvent(0, evS1, 0);
    gemm128i_kernel<<<cdiv(N1, 32), 256>>>(A, idx01, d201, pos1, W2, dv1, b2, N1, B, C);
    scatterS128_kernel<<<cdiv(cdiv(E1, SCHUNK) * 32, 256), 256>>>((const float4*)B, dv1, sr1, sc1, E1, (float4*)C);

    cudaStreamWaitEvent(0, evK12, 0);
    cudaStreamWaitEvent(0, evS2, 0);
    gemm128i_kernel<<<cdiv(N2, 32), 256>>>(C, idx12, d212, pos2, W3, dv2, b3, N2, A, B);
    scatterS128_kernel<<<cdiv(cdiv(E2, SCHUNK) * 32, 256), 256>>>((const float4*)A, dv2, sr2, sc2, E2, (float4*)B);

    gemm5_kernel<<<cdiv(N2, 25), 128>>>(B, pos2, W4, dv2, b4, N2, C, out, 1);
    scatterS5_kernel<<<cdiv(cdiv(E2, SCHUNK), 256), 256>>>(C, dv2, sr2, sc2, E2, out);

    // join
    cudaStreamWaitEvent(0, evDegDone, 0);
    cudaStreamWaitEvent(0, evGeo0Done, 0);
    cudaStreamWaitEvent(0, evKnn2Done, 0);
}